// round 7
// baseline (speedup 1.0000x reference)
#include <cuda_runtime.h>
#include <cuda_fp16.h>
#include <cstdint>

// ---------------------------------------------------------------------------
// Swin shifted-window attention, B=32 H=W=56 C=256, 7x7 win, shift 3, 8 heads.
//
//  1) convert weights -> fp16 hi(W)  [N,256]
//  2) QKV GEMM  (fused fp32-A hi/lo split, mma.sync f16): qkv fp16 [M,768]
//     A fragments loaded as fp32 straight from global, split into hi/lo half2
//     in registers; 2 MMAs (hi,lo) per B fragment into one fp32 accumulator.
//  3) windowed attention: per-(window,head) tensor-core MMA (49 padded to 64),
//     fused bias+mask+softmax on fragments -> acat fp32 [M,256]
//  4) proj GEMM (same fused kernel): d_out[M,256] fp32
// ---------------------------------------------------------------------------

#define M_ROWS 100352           // 32*56*56

__device__ __half g_qkv[100352ULL * 768];
__device__ float  g_acat[100352ULL * 256];
__device__ __half g_wq[768ULL * 256];
__device__ __half g_wp[256ULL * 256];

// ======================= helpers ============================================
__device__ __forceinline__ uint32_t smem_u32(const void* p) {
    uint32_t a;
    asm("{ .reg .u64 t; cvta.to.shared.u64 t, %1; cvt.u32.u64 %0, t; }"
        : "=r"(a) : "l"(p));
    return a;
}
__device__ __forceinline__ uint32_t h2u(__half2 h) {
    union { __half2 h; uint32_t u; } c;
    c.h = h;
    return c.u;
}
__device__ __forceinline__ void cp16(uint32_t s, const void* g) {
    asm volatile("cp.async.cg.shared.global [%0], [%1], 16;"
                 :: "r"(s), "l"(g) : "memory");
}
#define CP_COMMIT() asm volatile("cp.async.commit_group;" ::: "memory")
#define CP_WAIT2()  asm volatile("cp.async.wait_group 2;" ::: "memory")

__device__ __forceinline__ void ldsm4(uint32_t& r0, uint32_t& r1,
                                      uint32_t& r2, uint32_t& r3, uint32_t a) {
    asm volatile("ldmatrix.sync.aligned.m8n8.x4.shared.b16 {%0,%1,%2,%3}, [%4];"
                 : "=r"(r0), "=r"(r1), "=r"(r2), "=r"(r3) : "r"(a));
}
__device__ __forceinline__ void ldsm4t(uint32_t& r0, uint32_t& r1,
                                       uint32_t& r2, uint32_t& r3, uint32_t a) {
    asm volatile(
        "ldmatrix.sync.aligned.m8n8.x4.trans.shared.b16 {%0,%1,%2,%3}, [%4];"
        : "=r"(r0), "=r"(r1), "=r"(r2), "=r"(r3) : "r"(a));
}
__device__ __forceinline__ void mma16816(float* c, const uint32_t* a,
                                         const uint32_t* b) {
    asm volatile(
        "mma.sync.aligned.m16n8k16.row.col.f32.f16.f16.f32 "
        "{%0,%1,%2,%3}, {%4,%5,%6,%7}, {%8,%9}, {%0,%1,%2,%3};"
        : "+f"(c[0]), "+f"(c[1]), "+f"(c[2]), "+f"(c[3])
        : "r"(a[0]), "r"(a[1]), "r"(a[2]), "r"(a[3]), "r"(b[0]), "r"(b[1]));
}

// ======================= weight conversion (hi only) ========================
__global__ void __launch_bounds__(256)
convert_w(const float* __restrict__ in, __half* __restrict__ out, int total4) {
    int t = blockIdx.x * 256 + threadIdx.x;
    if (t >= total4) return;
    float4 v = *(const float4*)(in + (size_t)t * 4);
    __half2 h0 = __floats2half2_rn(v.x, v.y);
    __half2 h1 = __floats2half2_rn(v.z, v.w);
    *(__half2*)(out + (size_t)t * 4)     = h0;
    *(__half2*)(out + (size_t)t * 4 + 2) = h1;
}

// ======================= fused fp32-A GEMM ==================================
// C[M,N] = A[M,256](fp32) @ W[N,256](fp16 hi)^T + bias, with in-register
// hi/lo split of A (2-term compensated fp16). CTA 128x128, 512 threads,
// 16 warps (4x4), warp tile 32x32. B via 4-stage cp.async, A via direct LDG.
#define BSTG 10240                     // 128 rows * 80B padded

template <typename OT>
__global__ void __launch_bounds__(512, 1)
gemm_fused(const float* __restrict__ A, const __half* __restrict__ W,
           const float* __restrict__ bias, OT* __restrict__ C, int N) {
    __shared__ __half sB[4][128 * 40];

    const int tid  = threadIdx.x;
    const int wid  = tid >> 5;         // 0..15
    const int lane = tid & 31;
    const int wm   = wid & 3;          // 4 warps over M
    const int wn   = wid >> 2;         // 4 warps over N
    const size_t m0 = (size_t)blockIdx.y * 128;
    const int    n0 = blockIdx.x * 128;
    const int g  = lane >> 2;
    const int t4 = lane & 3;

    float acc[2][4][4];
#pragma unroll
    for (int i = 0; i < 2; i++)
#pragma unroll
        for (int j = 0; j < 4; j++)
#pragma unroll
            for (int k = 0; k < 4; k++) acc[i][j][k] = 0.f;

    // ---- B cp.async mapping: one 16B chunk per thread per stage ----
    const int r_ = tid >> 2;           // 0..127
    const int c_ = tid & 3;            // 0..3
    const __half* gB = W + (size_t)(n0 + r_) * 256 + c_ * 8;
    const uint32_t sB0 = smem_u32(&sB[0][0]);
    const uint32_t stOff = (r_ * 5 + c_) * 16;

#define LDB(st, k0) cp16(sB0 + (st) * BSTG + stOff, gB + (k0))

    // ---- A base pointer (fp32, direct LDG) ----
    const float* aBase = A + (m0 + wm * 32 + g) * 256 + 2 * t4;

#define LOAD_A(F, kb)                                                        \
    do {                                                                     \
        _Pragma("unroll")                                                    \
        for (int mt = 0; mt < 2; mt++) {                                     \
            const float* p = aBase + mt * 16 * 256 + (kb);                   \
            (F)[mt][0] = *(const float2*)(p);                                \
            (F)[mt][1] = *(const float2*)(p + 8 * 256);                      \
            (F)[mt][2] = *(const float2*)(p + 8);                            \
            (F)[mt][3] = *(const float2*)(p + 8 * 256 + 8);                  \
        }                                                                    \
    } while (0)

#define DO_KK(F, bb, kk)                                                     \
    do {                                                                     \
        uint32_t ah[2][4], al[2][4];                                         \
        _Pragma("unroll")                                                    \
        for (int mt = 0; mt < 2; mt++)                                       \
            _Pragma("unroll")                                                \
            for (int j = 0; j < 4; j++) {                                    \
                __half2 h = __floats2half2_rn((F)[mt][j].x, (F)[mt][j].y);   \
                float2 hf = __half22float2(h);                               \
                __half2 l = __floats2half2_rn((F)[mt][j].x - hf.x,           \
                                              (F)[mt][j].y - hf.y);          \
                ah[mt][j] = h2u(h);                                          \
                al[mt][j] = h2u(l);                                          \
            }                                                                \
        uint32_t bf[4][2];                                                   \
        _Pragma("unroll")                                                    \
        for (int pr = 0; pr < 2; pr++) {                                     \
            int row = wn * 32 + pr * 16 + (lane & 7) + ((lane >> 4) << 3);   \
            uint32_t ad = (bb) + (row * 5 + (kk) * 2 + ((lane >> 3) & 1)) * 16; \
            uint32_t q0, q1, q2, q3;                                         \
            ldsm4(q0, q1, q2, q3, ad);                                       \
            bf[2 * pr][0] = q0;     bf[2 * pr][1] = q1;                      \
            bf[2 * pr + 1][0] = q2; bf[2 * pr + 1][1] = q3;                  \
        }                                                                    \
        _Pragma("unroll")                                                    \
        for (int mt = 0; mt < 2; mt++)                                       \
            _Pragma("unroll")                                                \
            for (int nt = 0; nt < 4; nt++) {                                 \
                mma16816(acc[mt][nt], ah[mt], bf[nt]);                       \
                mma16816(acc[mt][nt], al[mt], bf[nt]);                       \
            }                                                                \
    } while (0)

    // prologue: B stages 0..2
    LDB(0, 0);  CP_COMMIT();
    LDB(1, 32); CP_COMMIT();
    LDB(2, 64); CP_COMMIT();

    float2 P[2][4];
    LOAD_A(P, 0);                      // chunk 0, kk=0

    for (int c = 0; c < 8; c++) {
        CP_WAIT2();
        __syncthreads();
        const uint32_t bb = sB0 + (c & 3) * BSTG;

        float2 Q[2][4];
        LOAD_A(Q, c * 32 + 16);        // kk=1 of this chunk
        DO_KK(P, bb, 0);
        if (c < 7) LOAD_A(P, (c + 1) * 32);   // kk=0 of next chunk
        DO_KK(Q, bb, 1);

        if (c + 3 < 8) LDB((c + 3) & 3, (c + 3) * 32);
        CP_COMMIT();
    }

    // ---- epilogue ----
#pragma unroll
    for (int nt = 0; nt < 4; nt++) {
        const int col = n0 + wn * 32 + nt * 8 + 2 * t4;
        float2 bb = *(const float2*)(bias + col);
#pragma unroll
        for (int mt = 0; mt < 2; mt++) {
            size_t row0 = m0 + wm * 32 + mt * 16 + g;
            float v00 = acc[mt][nt][0] + bb.x, v01 = acc[mt][nt][1] + bb.y;
            float v10 = acc[mt][nt][2] + bb.x, v11 = acc[mt][nt][3] + bb.y;
            if constexpr (sizeof(OT) == 4) {
                *(float2*)((float*)C + row0 * N + col) = make_float2(v00, v01);
                *(float2*)((float*)C + (row0 + 8) * N + col) = make_float2(v10, v11);
            } else {
                *(__half2*)((__half*)C + row0 * N + col) =
                    __floats2half2_rn(v00, v01);
                *(__half2*)((__half*)C + (row0 + 8) * N + col) =
                    __floats2half2_rn(v10, v11);
            }
        }
    }
#undef LDB
#undef LOAD_A
#undef DO_KK
}

// ======================= tensor-core attention ==============================
__global__ void __launch_bounds__(64)
attn_mma(const __half* __restrict__ qkv, const float* __restrict__ table,
         float* __restrict__ outp) {
    __shared__ __align__(16) __half Qs[64 * 40];
    __shared__ __align__(16) __half Ks[64 * 40];
    __shared__ __align__(16) __half Vs[64 * 40];
    __shared__ float Bs[169];
    __shared__ int   rowi[49];
    __shared__ int   cinfo[64];

    const int tid  = threadIdx.x;
    const int w    = tid >> 5;
    const int lane = tid & 31;
    const int head = blockIdx.x & 7;
    const int win  = blockIdx.x >> 3;
    const int b    = win >> 6;
    const int wr   = (win >> 3) & 7;
    const int wc   = win & 7;

    if (tid < 49) {
        int ih = tid / 7, iw = tid - ih * 7;
        int oh = wr * 7 + ih + 3; if (oh >= 56) oh -= 56;
        int ow = wc * 7 + iw + 3; if (ow >= 56) ow -= 56;
        rowi[tid] = (b * 56 + oh) * 56 + ow;
    }
    {
        int j = tid;
        int jh = j / 7, jw = j - jh * 7;
        int hj = wr * 7 + jh, wj = wc * 7 + jw;
        int rj = ((hj < 49) ? 0 : (hj < 53 ? 1 : 2)) * 3 +
                 ((wj < 49) ? 0 : (wj < 53 ? 1 : 2));
        cinfo[j] = (jh * 13 + jw) | (rj << 8) | ((j < 49 ? 0 : 1) << 15);
    }
    for (int t = tid; t < 169; t += 64) Bs[t] = table[t * 8 + head];
    for (int idx = tid; idx < 180; idx += 64) {
        int mat = idx / 60, rem = idx - mat * 60;
        int r = 49 + (rem >> 2), q = rem & 3;
        __half* base = (mat == 0) ? Qs : (mat == 1) ? Ks : Vs;
        *(uint4*)(base + r * 40 + q * 8) = make_uint4(0, 0, 0, 0);
    }
    __syncthreads();

    for (int idx = tid; idx < 196; idx += 64) {
        int p = idx >> 2, q = idx & 3;
        const __half* src = qkv + (size_t)rowi[p] * 768 + head * 32 + q * 8;
        *(uint4*)(Qs + p * 40 + q * 8) = *(const uint4*)(src);
        *(uint4*)(Ks + p * 40 + q * 8) = *(const uint4*)(src + 256);
        *(uint4*)(Vs + p * 40 + q * 8) = *(const uint4*)(src + 512);
    }
    __syncthreads();

    const uint32_t sQ = smem_u32(Qs), sK = smem_u32(Ks), sV = smem_u32(Vs);

    uint32_t aQ[2][2][4];
#pragma unroll
    for (int mt = 0; mt < 2; mt++)
#pragma unroll
        for (int kk = 0; kk < 2; kk++) {
            int row = w * 32 + mt * 16 + (lane & 15);
            uint32_t ad = sQ + row * 80 + (kk * 2 + (lane >> 4)) * 16;
            ldsm4(aQ[mt][kk][0], aQ[mt][kk][1], aQ[mt][kk][2], aQ[mt][kk][3], ad);
        }
    uint32_t bK[2][8][2];
#pragma unroll
    for (int kk = 0; kk < 2; kk++)
#pragma unroll
        for (int pr = 0; pr < 4; pr++) {
            int row = pr * 16 + (lane & 7) + ((lane >> 4) << 3);
            uint32_t ad = sK + row * 80 + (kk * 2 + ((lane >> 3) & 1)) * 16;
            uint32_t r0, r1, r2, r3;
            ldsm4(r0, r1, r2, r3, ad);
            bK[kk][2 * pr][0] = r0;     bK[kk][2 * pr][1] = r1;
            bK[kk][2 * pr + 1][0] = r2; bK[kk][2 * pr + 1][1] = r3;
        }
    float s[2][8][4];
#pragma unroll
    for (int mt = 0; mt < 2; mt++)
#pragma unroll
        for (int nt = 0; nt < 8; nt++) {
            s[mt][nt][0] = s[mt][nt][1] = s[mt][nt][2] = s[mt][nt][3] = 0.f;
            mma16816(s[mt][nt], aQ[mt][0], bK[0][nt]);
            mma16816(s[mt][nt], aQ[mt][1], bK[1][nt]);
        }

    const int g  = lane >> 2;
    const int t4 = lane & 3;
    const float scale = 0.17677669529663687f;

    int cp[16];
#pragma unroll
    for (int nt = 0; nt < 8; nt++) {
        cp[2 * nt]     = cinfo[nt * 8 + 2 * t4];
        cp[2 * nt + 1] = cinfo[nt * 8 + 2 * t4 + 1];
    }
    int   rb[2][2], ri[2][2];
    bool  rv[2][2];
#pragma unroll
    for (int mt = 0; mt < 2; mt++)
#pragma unroll
        for (int h = 0; h < 2; h++) {
            int i = w * 32 + mt * 16 + g + 8 * h;
            rv[mt][h] = (i < 49);
            int ih = i / 7, iw = i - ih * 7;
            if (!rv[mt][h]) { ih = 0; iw = 0; }
            rb[mt][h] = (ih + 6) * 13 + iw + 6;
            int hh = wr * 7 + ih, vv = wc * 7 + iw;
            ri[mt][h] = ((hh < 49) ? 0 : (hh < 53 ? 1 : 2)) * 3 +
                        ((vv < 49) ? 0 : (vv < 53 ? 1 : 2));
        }
#pragma unroll
    for (int mt = 0; mt < 2; mt++)
#pragma unroll
        for (int nt = 0; nt < 8; nt++)
#pragma unroll
            for (int e = 0; e < 4; e++) {
                int h = e >> 1, cs = e & 1;
                float v;
                if (!rv[mt][h]) v = 0.f;
                else {
                    int ci = cp[2 * nt + cs];
                    if (ci >> 15) v = -1e4f;
                    else {
                        v = s[mt][nt][e] * scale + Bs[rb[mt][h] - (ci & 0xFF)];
                        if (((ci >> 8) & 0xF) != ri[mt][h]) v -= 100.f;
                    }
                }
                s[mt][nt][e] = v;
            }

    float zinv[2][2];
#pragma unroll
    for (int mt = 0; mt < 2; mt++)
#pragma unroll
        for (int h = 0; h < 2; h++) {
            float m = -1e30f;
#pragma unroll
            for (int nt = 0; nt < 8; nt++) {
                m = fmaxf(m, s[mt][nt][2 * h]);
                m = fmaxf(m, s[mt][nt][2 * h + 1]);
            }
            m = fmaxf(m, __shfl_xor_sync(0xffffffffu, m, 1));
            m = fmaxf(m, __shfl_xor_sync(0xffffffffu, m, 2));
            float sum = 0.f;
#pragma unroll
            for (int nt = 0; nt < 8; nt++) {
                float e0 = __expf(s[mt][nt][2 * h] - m);
                float e1 = __expf(s[mt][nt][2 * h + 1] - m);
                s[mt][nt][2 * h] = e0;
                s[mt][nt][2 * h + 1] = e1;
                sum += e0 + e1;
            }
            sum += __shfl_xor_sync(0xffffffffu, sum, 1);
            sum += __shfl_xor_sync(0xffffffffu, sum, 2);
            zinv[mt][h] = 1.0f / sum;
        }

    uint32_t aP[2][4][4];
#pragma unroll
    for (int mt = 0; mt < 2; mt++)
#pragma unroll
        for (int kt = 0; kt < 4; kt++) {
            aP[mt][kt][0] = h2u(__floats2half2_rn(s[mt][2 * kt][0],
                                                  s[mt][2 * kt][1]));
            aP[mt][kt][1] = h2u(__floats2half2_rn(s[mt][2 * kt][2],
                                                  s[mt][2 * kt][3]));
            aP[mt][kt][2] = h2u(__floats2half2_rn(s[mt][2 * kt + 1][0],
                                                  s[mt][2 * kt + 1][1]));
            aP[mt][kt][3] = h2u(__floats2half2_rn(s[mt][2 * kt + 1][2],
                                                  s[mt][2 * kt + 1][3]));
        }

    uint32_t bV[4][4][2];
#pragma unroll
    for (int kt = 0; kt < 4; kt++)
#pragma unroll
        for (int nh = 0; nh < 2; nh++) {
            int row = kt * 16 + (lane & 7) + (((lane >> 3) & 1) << 3);
            uint32_t ad = sV + row * 80 + nh * 32 + ((lane >> 4) << 4);
            uint32_t r0, r1, r2, r3;
            ldsm4t(r0, r1, r2, r3, ad);
            bV[kt][2 * nh][0] = r0;     bV[kt][2 * nh][1] = r1;
            bV[kt][2 * nh + 1][0] = r2; bV[kt][2 * nh + 1][1] = r3;
        }

    float o[2][4][4];
#pragma unroll
    for (int mt = 0; mt < 2; mt++)
#pragma unroll
        for (int vn = 0; vn < 4; vn++) {
            o[mt][vn][0] = o[mt][vn][1] = o[mt][vn][2] = o[mt][vn][3] = 0.f;
#pragma unroll
            for (int kt = 0; kt < 4; kt++)
                mma16816(o[mt][vn], aP[mt][kt], bV[kt][vn]);
        }

#pragma unroll
    for (int mt = 0; mt < 2; mt++)
#pragma unroll
        for (int h = 0; h < 2; h++) {
            int i = w * 32 + mt * 16 + g + 8 * h;
            if (i >= 49) continue;
            float rz = zinv[mt][h];
            float* dst = outp + (size_t)rowi[i] * 256 + head * 32;
#pragma unroll
            for (int vn = 0; vn < 4; vn++) {
                int col = vn * 8 + 2 * t4;
                *(float2*)(dst + col) =
                    make_float2(o[mt][vn][2 * h] * rz,
                                o[mt][vn][2 * h + 1] * rz);
            }
        }
}

// ---------------------------------------------------------------------------
extern "C" void kernel_launch(void* const* d_in, const int* in_sizes, int n_in,
                              void* d_out, int out_size) {
    const float* x      = (const float*)d_in[0];
    const float* qkv_w  = (const float*)d_in[1];
    const float* qkv_b  = (const float*)d_in[2];
    const float* proj_w = (const float*)d_in[3];
    const float* proj_b = (const float*)d_in[4];
    const float* table  = (const float*)d_in[5];
    float* out = (float*)d_out;

    void *qkv_p, *acat_p, *wq_p, *wp_p;
    cudaGetSymbolAddress(&qkv_p,  g_qkv);
    cudaGetSymbolAddress(&acat_p, g_acat);
    cudaGetSymbolAddress(&wq_p,   g_wq);
    cudaGetSymbolAddress(&wp_p,   g_wp);
    __half* qkv  = (__half*)qkv_p;
    float*  acat = (float*)acat_p;
    __half* wq   = (__half*)wq_p;
    __half* wp   = (__half*)wp_p;

    convert_w<<<(768 * 64 + 255) / 256, 256>>>(qkv_w, wq, 768 * 64);
    convert_w<<<(256 * 64 + 255) / 256, 256>>>(proj_w, wp, 256 * 64);

    // QKV: M=100352, N=768 (A = x fp32, split in-register)
    dim3 gq(768 / 128, M_ROWS / 128);
    gemm_fused<__half><<<gq, 512>>>(x, wq, qkv_b, qkv, 768);

    attn_mma<<<2048 * 8, 64>>>(qkv, table, acat);

    // proj: M=100352, N=256 (A = attention out fp32)
    dim3 gp(256 / 128, M_ROWS / 128);
    gemm_fused<float><<<gp, 512>>>(acat, wp, proj_b, out, 256);
}

// round 8
// speedup vs baseline: 1.3324x; 1.3324x over previous
#include <cuda_runtime.h>
#include <cuda_fp16.h>
#include <cstdint>

// ---------------------------------------------------------------------------
// Swin shifted-window attention, B=32 H=W=56 C=256, 7x7 win, shift 3, 8 heads.
//
//  1) convert x -> x_cat fp16 [M,512] = [hi | lo]      (2-term K-split)
//     convert w -> w_cat fp16 [N,512] = [hi | hi]
//  2) QKV GEMM (mma.sync f16, fp32 acc, 4-stage cp.async) -> g_qkv fp16 [M,768]
//  3) windowed attention: 4 heads per block, tensor-core MMA (49 padded to 64),
//     fused bias+mask+softmax on fragments, writes acat fp16 [M,512] split
//  4) proj GEMM: d_out[M,256] fp32
// ---------------------------------------------------------------------------

#define M_ROWS 100352           // 32*56*56
#define KH     512              // 2*256 split-K fp16

__device__ __half g_qkv[100352ULL * 768];
__device__ __half g_xcat[100352ULL * 512];
__device__ __half g_acat[100352ULL * 512];
__device__ __half g_wq[768ULL * 512];
__device__ __half g_wp[256ULL * 512];

// ======================= helpers ============================================
__device__ __forceinline__ uint32_t smem_u32(const void* p) {
    uint32_t a;
    asm("{ .reg .u64 t; cvta.to.shared.u64 t, %1; cvt.u32.u64 %0, t; }"
        : "=r"(a) : "l"(p));
    return a;
}
__device__ __forceinline__ uint32_t h2u(__half2 h) {
    union { __half2 h; uint32_t u; } c;
    c.h = h;
    return c.u;
}
__device__ __forceinline__ void cp16(uint32_t s, const void* g) {
    asm volatile("cp.async.cg.shared.global [%0], [%1], 16;"
                 :: "r"(s), "l"(g) : "memory");
}
#define CP_COMMIT() asm volatile("cp.async.commit_group;" ::: "memory")
#define CP_WAIT2()  asm volatile("cp.async.wait_group 2;" ::: "memory")

__device__ __forceinline__ void ldsm4(uint32_t& r0, uint32_t& r1,
                                      uint32_t& r2, uint32_t& r3, uint32_t a) {
    asm volatile("ldmatrix.sync.aligned.m8n8.x4.shared.b16 {%0,%1,%2,%3}, [%4];"
                 : "=r"(r0), "=r"(r1), "=r"(r2), "=r"(r3) : "r"(a));
}
__device__ __forceinline__ void ldsm4t(uint32_t& r0, uint32_t& r1,
                                       uint32_t& r2, uint32_t& r3, uint32_t a) {
    asm volatile(
        "ldmatrix.sync.aligned.m8n8.x4.trans.shared.b16 {%0,%1,%2,%3}, [%4];"
        : "=r"(r0), "=r"(r1), "=r"(r2), "=r"(r3) : "r"(a));
}
__device__ __forceinline__ void mma16816(float* c, const uint32_t* a,
                                         const uint32_t* b) {
    asm volatile(
        "mma.sync.aligned.m16n8k16.row.col.f32.f16.f16.f32 "
        "{%0,%1,%2,%3}, {%4,%5,%6,%7}, {%8,%9}, {%0,%1,%2,%3};"
        : "+f"(c[0]), "+f"(c[1]), "+f"(c[2]), "+f"(c[3])
        : "r"(a[0]), "r"(a[1]), "r"(a[2]), "r"(a[3]), "r"(b[0]), "r"(b[1]));
}

// ======================= split-fp16 conversion ==============================
__global__ void __launch_bounds__(256)
convert_split(const float* __restrict__ in, __half* __restrict__ out,
              int nrows, int dupHi) {
    int t = blockIdx.x * 256 + threadIdx.x;
    if (t >= nrows * 64) return;
    int m = t >> 6;
    int c = (t & 63) << 2;
    float4 v = *(const float4*)(in + (size_t)m * 256 + c);

    __half hx = __float2half_rn(v.x), hy = __float2half_rn(v.y);
    __half hz = __float2half_rn(v.z), hw = __float2half_rn(v.w);
    __half lx, ly, lz, lw;
    if (dupHi) { lx = hx; ly = hy; lz = hz; lw = hw; }
    else {
        lx = __float2half_rn(v.x - __half2float(hx));
        ly = __float2half_rn(v.y - __half2float(hy));
        lz = __float2half_rn(v.z - __half2float(hz));
        lw = __float2half_rn(v.w - __half2float(hw));
    }
    __half* base = out + (size_t)m * KH + c;
    *(__half2*)(base)       = __halves2half2(hx, hy);
    *(__half2*)(base + 2)   = __halves2half2(hz, hw);
    *(__half2*)(base + 256) = __halves2half2(lx, ly);
    *(__half2*)(base + 258) = __halves2half2(lz, lw);
}

// ======================= mma.sync GEMM (4-stage pipeline) ====================
#define GROW   40
#define ASZ    (128 * GROW * 2)
#define STAGEB (2 * ASZ)
#define NSTG   4
#define GEMM_SMEM (NSTG * STAGEB)     // 81920 B

template <typename OT>
__global__ void __launch_bounds__(256, 2)
gemm_mma(const __half* __restrict__ A, const __half* __restrict__ W,
         const float* __restrict__ bias, OT* __restrict__ C, int N) {
    extern __shared__ __half smbuf[];

    const int tid  = threadIdx.x;
    const int wid  = tid >> 5;
    const int lane = tid & 31;
    const int wm   = wid & 3;
    const int wn   = wid >> 2;
    const size_t m0 = (size_t)blockIdx.y * 128;
    const int    n0 = blockIdx.x * 128;

    float acc[2][8][4];
#pragma unroll
    for (int i = 0; i < 2; i++)
#pragma unroll
        for (int j = 0; j < 8; j++)
#pragma unroll
            for (int k = 0; k < 4; k++) acc[i][j][k] = 0.f;

    const int r_ = tid >> 2, c_ = tid & 3;
    const __half* gA = A + (m0 + r_) * KH + c_ * 8;
    const __half* gB = W + (size_t)(n0 + r_) * KH + c_ * 8;
    const uint32_t s0 = smem_u32(smbuf);
    const uint32_t stOff = (r_ * 5 + c_) * 16;

#define LOAD_SLAB(st, k0)                                                    \
    do {                                                                     \
        uint32_t ab = s0 + (st) * STAGEB;                                    \
        uint32_t bb = ab + ASZ;                                              \
        cp16(ab + stOff, gA + (k0));                                         \
        cp16(ab + stOff + 64 * 5 * 16, gA + (k0) + (size_t)64 * KH);         \
        cp16(bb + stOff, gB + (k0));                                         \
        cp16(bb + stOff + 64 * 5 * 16, gB + (k0) + (size_t)64 * KH);         \
    } while (0)

    const int NS = KH / 32;   // 16 slabs

#pragma unroll
    for (int i = 0; i < 3; i++) {
        LOAD_SLAB(i, i * 32);
        CP_COMMIT();
    }

    const int aRow = wm * 32 + (lane & 15);
    const int aChk = lane >> 4;
    const int bRowBase = wn * 64 + (lane & 7) + ((lane >> 4) << 3);
    const int bChk = (lane >> 3) & 1;

    for (int s = 0; s < NS; s++) {
        const int st = s & 3;
        CP_WAIT2();
        __syncthreads();

        const uint32_t aBase = s0 + st * STAGEB;
        const uint32_t bBase = aBase + ASZ;
#pragma unroll
        for (int kk = 0; kk < 2; kk++) {
            uint32_t af[2][4];
#pragma unroll
            for (int mt = 0; mt < 2; mt++) {
                uint32_t ad = aBase +
                    ((aRow + mt * 16) * 5 + kk * 2 + aChk) * 16;
                ldsm4(af[mt][0], af[mt][1], af[mt][2], af[mt][3], ad);
            }
            uint32_t bf[8][2];
#pragma unroll
            for (int pr = 0; pr < 4; pr++) {
                uint32_t bd = bBase +
                    ((bRowBase + pr * 16) * 5 + kk * 2 + bChk) * 16;
                uint32_t r0, r1, r2, r3;
                ldsm4(r0, r1, r2, r3, bd);
                bf[2 * pr][0] = r0; bf[2 * pr][1] = r1;
                bf[2 * pr + 1][0] = r2; bf[2 * pr + 1][1] = r3;
            }
#pragma unroll
            for (int mt = 0; mt < 2; mt++)
#pragma unroll
                for (int nt = 0; nt < 8; nt++)
                    mma16816(acc[mt][nt], af[mt], bf[nt]);
        }

        if (s + 3 < NS) LOAD_SLAB((s + 3) & 3, (s + 3) * 32);
        CP_COMMIT();
    }

    const int g  = lane >> 2;
    const int t4 = lane & 3;
#pragma unroll
    for (int nt = 0; nt < 8; nt++) {
        const int col = n0 + wn * 64 + nt * 8 + 2 * t4;
        float2 bb = *(const float2*)(bias + col);
#pragma unroll
        for (int mt = 0; mt < 2; mt++) {
            size_t row0 = m0 + wm * 32 + mt * 16 + g;
            float v00 = acc[mt][nt][0] + bb.x, v01 = acc[mt][nt][1] + bb.y;
            float v10 = acc[mt][nt][2] + bb.x, v11 = acc[mt][nt][3] + bb.y;
            if constexpr (sizeof(OT) == 4) {
                *(float2*)((float*)C + row0 * N + col) = make_float2(v00, v01);
                *(float2*)((float*)C + (row0 + 8) * N + col) = make_float2(v10, v11);
            } else {
                *(__half2*)((__half*)C + row0 * N + col) =
                    __floats2half2_rn(v00, v01);
                *(__half2*)((__half*)C + (row0 + 8) * N + col) =
                    __floats2half2_rn(v10, v11);
            }
        }
    }
#undef LOAD_SLAB
}

// ======================= tensor-core attention (4 heads/block) ==============
// Block = (window, head-group of 4), 256 threads (8 warps = 2 per head).
__global__ void __launch_bounds__(256)
attn_mma(const __half* __restrict__ qkv, const float* __restrict__ table,
         __half* __restrict__ outp) {
    __shared__ __align__(16) __half Qs[4][64 * 40];
    __shared__ __align__(16) __half Ks[4][64 * 40];
    __shared__ __align__(16) __half Vs[4][64 * 40];
    __shared__ float Bs[4][169];
    __shared__ int   rowi[49];
    __shared__ int   cinfo[64];

    const int tid  = threadIdx.x;
    const int wid  = tid >> 5;
    const int lane = tid & 31;
    const int hloc = wid >> 1;          // head within group 0..3
    const int w    = wid & 1;           // row-half of the 64-token tile
    const int hg   = blockIdx.x & 1;    // head group 0/1
    const int win  = blockIdx.x >> 1;
    const int b    = win >> 6;
    const int wr   = (win >> 3) & 7;
    const int wc   = win & 7;

    if (tid < 49) {
        int ih = tid / 7, iw = tid - ih * 7;
        int oh = wr * 7 + ih + 3; if (oh >= 56) oh -= 56;
        int ow = wc * 7 + iw + 3; if (ow >= 56) ow -= 56;
        rowi[tid] = (b * 56 + oh) * 56 + ow;
    }
    if (tid < 64) {
        int j = tid;
        int jh = j / 7, jw = j - jh * 7;
        int hj = wr * 7 + jh, wj = wc * 7 + jw;
        int rj = ((hj < 49) ? 0 : (hj < 53 ? 1 : 2)) * 3 +
                 ((wj < 49) ? 0 : (wj < 53 ? 1 : 2));
        cinfo[j] = (jh * 13 + jw) | (rj << 8) | ((j < 49 ? 0 : 1) << 15);
    }
    for (int t = tid; t < 676; t += 256) {
        int h = t / 169, idx = t - h * 169;
        Bs[h][idx] = table[idx * 8 + hg * 4 + h];
    }
    // zero pad rows 49..63 (15 rows x 4 chunks x 3 mats x 4 heads = 720)
    for (int idx = tid; idx < 720; idx += 256) {
        int h = idx / 180, rem = idx - h * 180;
        int mat = rem / 60, rem2 = rem - mat * 60;
        int r = 49 + (rem2 >> 2), q = rem2 & 3;
        __half* base = (mat == 0) ? &Qs[h][0] : (mat == 1) ? &Ks[h][0]
                                              : &Vs[h][0];
        *(uint4*)(base + r * 40 + q * 8) = make_uint4(0, 0, 0, 0);
    }
    __syncthreads();

    // gather Q,K,V: 49 rows x 128 halves (4 heads, 256B contiguous per mat)
    for (int idx = tid; idx < 784; idx += 256) {
        int p = idx >> 4, q = idx & 15;     // q: 16B chunk within 256B
        int h = q >> 2, c = q & 3;
        const __half* src = qkv + (size_t)rowi[p] * 768 + hg * 128 + q * 8;
        *(uint4*)(&Qs[h][0] + p * 40 + c * 8) = *(const uint4*)(src);
        *(uint4*)(&Ks[h][0] + p * 40 + c * 8) = *(const uint4*)(src + 256);
        *(uint4*)(&Vs[h][0] + p * 40 + c * 8) = *(const uint4*)(src + 512);
    }
    __syncthreads();

    const uint32_t sQ = smem_u32(&Qs[hloc][0]);
    const uint32_t sK = smem_u32(&Ks[hloc][0]);
    const uint32_t sV = smem_u32(&Vs[hloc][0]);
    const float*   Bh = &Bs[hloc][0];
    const int head = hg * 4 + hloc;

    // ---- S = Q K^T ----
    uint32_t aQ[2][2][4];
#pragma unroll
    for (int mt = 0; mt < 2; mt++)
#pragma unroll
        for (int kk = 0; kk < 2; kk++) {
            int row = w * 32 + mt * 16 + (lane & 15);
            uint32_t ad = sQ + row * 80 + (kk * 2 + (lane >> 4)) * 16;
            ldsm4(aQ[mt][kk][0], aQ[mt][kk][1], aQ[mt][kk][2], aQ[mt][kk][3], ad);
        }
    uint32_t bK[2][8][2];
#pragma unroll
    for (int kk = 0; kk < 2; kk++)
#pragma unroll
        for (int pr = 0; pr < 4; pr++) {
            int row = pr * 16 + (lane & 7) + ((lane >> 4) << 3);
            uint32_t ad = sK + row * 80 + (kk * 2 + ((lane >> 3) & 1)) * 16;
            uint32_t r0, r1, r2, r3;
            ldsm4(r0, r1, r2, r3, ad);
            bK[kk][2 * pr][0] = r0;     bK[kk][2 * pr][1] = r1;
            bK[kk][2 * pr + 1][0] = r2; bK[kk][2 * pr + 1][1] = r3;
        }
    float s[2][8][4];
#pragma unroll
    for (int mt = 0; mt < 2; mt++)
#pragma unroll
        for (int nt = 0; nt < 8; nt++) {
            s[mt][nt][0] = s[mt][nt][1] = s[mt][nt][2] = s[mt][nt][3] = 0.f;
            mma16816(s[mt][nt], aQ[mt][0], bK[0][nt]);
            mma16816(s[mt][nt], aQ[mt][1], bK[1][nt]);
        }

    const int g  = lane >> 2;
    const int t4 = lane & 3;
    const float scale = 0.17677669529663687f;

    int cp[16];
#pragma unroll
    for (int nt = 0; nt < 8; nt++) {
        cp[2 * nt]     = cinfo[nt * 8 + 2 * t4];
        cp[2 * nt + 1] = cinfo[nt * 8 + 2 * t4 + 1];
    }
    int   rb[2][2], ri[2][2];
    bool  rv[2][2];
#pragma unroll
    for (int mt = 0; mt < 2; mt++)
#pragma unroll
        for (int h = 0; h < 2; h++) {
            int i = w * 32 + mt * 16 + g + 8 * h;
            rv[mt][h] = (i < 49);
            int ih = i / 7, iw = i - ih * 7;
            if (!rv[mt][h]) { ih = 0; iw = 0; }
            rb[mt][h] = (ih + 6) * 13 + iw + 6;
            int hh = wr * 7 + ih, vv = wc * 7 + iw;
            ri[mt][h] = ((hh < 49) ? 0 : (hh < 53 ? 1 : 2)) * 3 +
                        ((vv < 49) ? 0 : (vv < 53 ? 1 : 2));
        }
#pragma unroll
    for (int mt = 0; mt < 2; mt++)
#pragma unroll
        for (int nt = 0; nt < 8; nt++)
#pragma unroll
            for (int e = 0; e < 4; e++) {
                int h = e >> 1, cs = e & 1;
                float v;
                if (!rv[mt][h]) v = 0.f;
                else {
                    int ci = cp[2 * nt + cs];
                    if (ci >> 15) v = -1e4f;
                    else {
                        v = s[mt][nt][e] * scale + Bh[rb[mt][h] - (ci & 0xFF)];
                        if (((ci >> 8) & 0xF) != ri[mt][h]) v -= 100.f;
                    }
                }
                s[mt][nt][e] = v;
            }

    float zinv[2][2];
#pragma unroll
    for (int mt = 0; mt < 2; mt++)
#pragma unroll
        for (int h = 0; h < 2; h++) {
            float m = -1e30f;
#pragma unroll
            for (int nt = 0; nt < 8; nt++) {
                m = fmaxf(m, s[mt][nt][2 * h]);
                m = fmaxf(m, s[mt][nt][2 * h + 1]);
            }
            m = fmaxf(m, __shfl_xor_sync(0xffffffffu, m, 1));
            m = fmaxf(m, __shfl_xor_sync(0xffffffffu, m, 2));
            float sum = 0.f;
#pragma unroll
            for (int nt = 0; nt < 8; nt++) {
                float e0 = __expf(s[mt][nt][2 * h] - m);
                float e1 = __expf(s[mt][nt][2 * h + 1] - m);
                s[mt][nt][2 * h] = e0;
                s[mt][nt][2 * h + 1] = e1;
                sum += e0 + e1;
            }
            sum += __shfl_xor_sync(0xffffffffu, sum, 1);
            sum += __shfl_xor_sync(0xffffffffu, sum, 2);
            zinv[mt][h] = 1.0f / sum;
        }

    uint32_t aP[2][4][4];
#pragma unroll
    for (int mt = 0; mt < 2; mt++)
#pragma unroll
        for (int kt = 0; kt < 4; kt++) {
            aP[mt][kt][0] = h2u(__floats2half2_rn(s[mt][2 * kt][0],
                                                  s[mt][2 * kt][1]));
            aP[mt][kt][1] = h2u(__floats2half2_rn(s[mt][2 * kt][2],
                                                  s[mt][2 * kt][3]));
            aP[mt][kt][2] = h2u(__floats2half2_rn(s[mt][2 * kt + 1][0],
                                                  s[mt][2 * kt + 1][1]));
            aP[mt][kt][3] = h2u(__floats2half2_rn(s[mt][2 * kt + 1][2],
                                                  s[mt][2 * kt + 1][3]));
        }

    uint32_t bV[4][4][2];
#pragma unroll
    for (int kt = 0; kt < 4; kt++)
#pragma unroll
        for (int nh = 0; nh < 2; nh++) {
            int row = kt * 16 + (lane & 7) + (((lane >> 3) & 1) << 3);
            uint32_t ad = sV + row * 80 + nh * 32 + ((lane >> 4) << 4);
            uint32_t r0, r1, r2, r3;
            ldsm4t(r0, r1, r2, r3, ad);
            bV[kt][2 * nh][0] = r0;     bV[kt][2 * nh][1] = r1;
            bV[kt][2 * nh + 1][0] = r2; bV[kt][2 * nh + 1][1] = r3;
        }

    float o[2][4][4];
#pragma unroll
    for (int mt = 0; mt < 2; mt++)
#pragma unroll
        for (int vn = 0; vn < 4; vn++) {
            o[mt][vn][0] = o[mt][vn][1] = o[mt][vn][2] = o[mt][vn][3] = 0.f;
#pragma unroll
            for (int kt = 0; kt < 4; kt++)
                mma16816(o[mt][vn], aP[mt][kt], bV[kt][vn]);
        }

#pragma unroll
    for (int mt = 0; mt < 2; mt++)
#pragma unroll
        for (int h = 0; h < 2; h++) {
            int i = w * 32 + mt * 16 + g + 8 * h;
            if (i >= 49) continue;
            float rz = zinv[mt][h];
            __half* dst = outp + (size_t)rowi[i] * KH + head * 32;
#pragma unroll
            for (int vn = 0; vn < 4; vn++) {
                int col = vn * 8 + 2 * t4;
                float v0 = o[mt][vn][2 * h] * rz;
                float v1 = o[mt][vn][2 * h + 1] * rz;
                __half h0 = __float2half_rn(v0), h1 = __float2half_rn(v1);
                __half l0 = __float2half_rn(v0 - __half2float(h0));
                __half l1 = __float2half_rn(v1 - __half2float(h1));
                *(__half2*)(dst + col)       = __halves2half2(h0, h1);
                *(__half2*)(dst + 256 + col) = __halves2half2(l0, l1);
            }
        }
}

// ---------------------------------------------------------------------------
extern "C" void kernel_launch(void* const* d_in, const int* in_sizes, int n_in,
                              void* d_out, int out_size) {
    const float* x      = (const float*)d_in[0];
    const float* qkv_w  = (const float*)d_in[1];
    const float* qkv_b  = (const float*)d_in[2];
    const float* proj_w = (const float*)d_in[3];
    const float* proj_b = (const float*)d_in[4];
    const float* table  = (const float*)d_in[5];
    float* out = (float*)d_out;

    void *qkv_p, *xcat_p, *acat_p, *wq_p, *wp_p;
    cudaGetSymbolAddress(&qkv_p,  g_qkv);
    cudaGetSymbolAddress(&xcat_p, g_xcat);
    cudaGetSymbolAddress(&acat_p, g_acat);
    cudaGetSymbolAddress(&wq_p,   g_wq);
    cudaGetSymbolAddress(&wp_p,   g_wp);
    __half* qkv  = (__half*)qkv_p;
    __half* xcat = (__half*)xcat_p;
    __half* acat = (__half*)acat_p;
    __half* wq   = (__half*)wq_p;
    __half* wp   = (__half*)wp_p;

    static bool attr_done = false;
    if (!attr_done) {
        cudaFuncSetAttribute(gemm_mma<__half>,
                             cudaFuncAttributeMaxDynamicSharedMemorySize,
                             GEMM_SMEM);
        cudaFuncSetAttribute(gemm_mma<float>,
                             cudaFuncAttributeMaxDynamicSharedMemorySize,
                             GEMM_SMEM);
        attr_done = true;
    }

    convert_split<<<(M_ROWS * 64 + 255) / 256, 256>>>(x, xcat, M_ROWS, 0);
    convert_split<<<(768 * 64 + 255) / 256, 256>>>(qkv_w, wq, 768, 1);
    convert_split<<<(256 * 64 + 255) / 256, 256>>>(proj_w, wp, 256, 1);

    dim3 gq(768 / 128, M_ROWS / 128);
    gemm_mma<__half><<<gq, 256, GEMM_SMEM>>>(xcat, wq, qkv_b, qkv, 768);

    attn_mma<<<2048 * 2, 256>>>(qkv, table, acat);

    dim3 gp(256 / 128, M_ROWS / 128);
    gemm_mma<float><<<gp, 256, GEMM_SMEM>>>(acat, wp, proj_b, out, 256);
}

// round 9
// speedup vs baseline: 1.9430x; 1.4583x over previous
#include <cuda_runtime.h>
#include <cuda_fp16.h>
#include <cstdint>

// ---------------------------------------------------------------------------
// Swin shifted-window attention, B=32 H=W=56 C=256, 7x7 win, shift 3, 8 heads.
// All GEMMs plain fp16 (K=256), fp32 accumulate.
//
//  1) convert x, qkv_w, proj_w -> fp16
//  2) QKV GEMM (mma.sync f16, 4-stage cp.async) -> g_qkv fp16 [M,768]
//  3) windowed attention: per-(window,head) tensor-core MMA (49 padded to 64),
//     fused bias+mask+softmax on fragments -> acat fp16 [M,256]
//  4) proj GEMM: d_out[M,256] fp32
// ---------------------------------------------------------------------------

#define M_ROWS 100352           // 32*56*56
#define KC     256

__device__ __half g_qkv[100352ULL * 768];
__device__ __half g_x16[100352ULL * 256];
__device__ __half g_acat[100352ULL * 256];
__device__ __half g_wq[768ULL * 256];
__device__ __half g_wp[256ULL * 256];

// ======================= helpers ============================================
__device__ __forceinline__ uint32_t smem_u32(const void* p) {
    uint32_t a;
    asm("{ .reg .u64 t; cvta.to.shared.u64 t, %1; cvt.u32.u64 %0, t; }"
        : "=r"(a) : "l"(p));
    return a;
}
__device__ __forceinline__ uint32_t h2u(__half2 h) {
    union { __half2 h; uint32_t u; } c;
    c.h = h;
    return c.u;
}
__device__ __forceinline__ void cp16(uint32_t s, const void* g) {
    asm volatile("cp.async.cg.shared.global [%0], [%1], 16;"
                 :: "r"(s), "l"(g) : "memory");
}
#define CP_COMMIT() asm volatile("cp.async.commit_group;" ::: "memory")
#define CP_WAIT2()  asm volatile("cp.async.wait_group 2;" ::: "memory")

__device__ __forceinline__ void ldsm4(uint32_t& r0, uint32_t& r1,
                                      uint32_t& r2, uint32_t& r3, uint32_t a) {
    asm volatile("ldmatrix.sync.aligned.m8n8.x4.shared.b16 {%0,%1,%2,%3}, [%4];"
                 : "=r"(r0), "=r"(r1), "=r"(r2), "=r"(r3) : "r"(a));
}
__device__ __forceinline__ void ldsm4t(uint32_t& r0, uint32_t& r1,
                                       uint32_t& r2, uint32_t& r3, uint32_t a) {
    asm volatile(
        "ldmatrix.sync.aligned.m8n8.x4.trans.shared.b16 {%0,%1,%2,%3}, [%4];"
        : "=r"(r0), "=r"(r1), "=r"(r2), "=r"(r3) : "r"(a));
}
__device__ __forceinline__ void mma16816(float* c, const uint32_t* a,
                                         const uint32_t* b) {
    asm volatile(
        "mma.sync.aligned.m16n8k16.row.col.f32.f16.f16.f32 "
        "{%0,%1,%2,%3}, {%4,%5,%6,%7}, {%8,%9}, {%0,%1,%2,%3};"
        : "+f"(c[0]), "+f"(c[1]), "+f"(c[2]), "+f"(c[3])
        : "r"(a[0]), "r"(a[1]), "r"(a[2]), "r"(a[3]), "r"(b[0]), "r"(b[1]));
}

// ======================= fp32 -> fp16 conversion ============================
__global__ void __launch_bounds__(256)
convert_h(const float* __restrict__ in, __half* __restrict__ out, int total4) {
    int t = blockIdx.x * 256 + threadIdx.x;
    if (t >= total4) return;
    float4 v = *(const float4*)(in + (size_t)t * 4);
    *(__half2*)(out + (size_t)t * 4)     = __floats2half2_rn(v.x, v.y);
    *(__half2*)(out + (size_t)t * 4 + 2) = __floats2half2_rn(v.z, v.w);
}

// ======================= mma.sync GEMM (4-stage pipeline) ====================
// C[M,N] = A[M,256] @ W[N,256]^T + bias. CTA 128x128, 8 warps (4x2),
// warp tile 32x64, BK=32, 4-stage cp.async circular buffer.
#define GROW   40
#define ASZ    (128 * GROW * 2)
#define STAGEB (2 * ASZ)
#define NSTG   4
#define GEMM_SMEM (NSTG * STAGEB)     // 81920 B

template <typename OT>
__global__ void __launch_bounds__(256, 2)
gemm_mma(const __half* __restrict__ A, const __half* __restrict__ W,
         const float* __restrict__ bias, OT* __restrict__ C, int N) {
    extern __shared__ __half smbuf[];

    const int tid  = threadIdx.x;
    const int wid  = tid >> 5;
    const int lane = tid & 31;
    const int wm   = wid & 3;
    const int wn   = wid >> 2;
    const size_t m0 = (size_t)blockIdx.y * 128;
    const int    n0 = blockIdx.x * 128;

    float acc[2][8][4];
#pragma unroll
    for (int i = 0; i < 2; i++)
#pragma unroll
        for (int j = 0; j < 8; j++)
#pragma unroll
            for (int k = 0; k < 4; k++) acc[i][j][k] = 0.f;

    const int r_ = tid >> 2, c_ = tid & 3;
    const __half* gA = A + (m0 + r_) * KC + c_ * 8;
    const __half* gB = W + (size_t)(n0 + r_) * KC + c_ * 8;
    const uint32_t s0 = smem_u32(smbuf);
    const uint32_t stOff = (r_ * 5 + c_) * 16;

#define LOAD_SLAB(st, k0)                                                    \
    do {                                                                     \
        uint32_t ab = s0 + (st) * STAGEB;                                    \
        uint32_t bb = ab + ASZ;                                              \
        cp16(ab + stOff, gA + (k0));                                         \
        cp16(ab + stOff + 64 * 5 * 16, gA + (k0) + (size_t)64 * KC);         \
        cp16(bb + stOff, gB + (k0));                                         \
        cp16(bb + stOff + 64 * 5 * 16, gB + (k0) + (size_t)64 * KC);         \
    } while (0)

    const int NS = KC / 32;   // 8 slabs

#pragma unroll
    for (int i = 0; i < 3; i++) {
        LOAD_SLAB(i, i * 32);
        CP_COMMIT();
    }

    const int aRow = wm * 32 + (lane & 15);
    const int aChk = lane >> 4;
    const int bRowBase = wn * 64 + (lane & 7) + ((lane >> 4) << 3);
    const int bChk = (lane >> 3) & 1;

    for (int s = 0; s < NS; s++) {
        const int st = s & 3;
        CP_WAIT2();
        __syncthreads();

        const uint32_t aBase = s0 + st * STAGEB;
        const uint32_t bBase = aBase + ASZ;
#pragma unroll
        for (int kk = 0; kk < 2; kk++) {
            uint32_t af[2][4];
#pragma unroll
            for (int mt = 0; mt < 2; mt++) {
                uint32_t ad = aBase +
                    ((aRow + mt * 16) * 5 + kk * 2 + aChk) * 16;
                ldsm4(af[mt][0], af[mt][1], af[mt][2], af[mt][3], ad);
            }
            uint32_t bf[8][2];
#pragma unroll
            for (int pr = 0; pr < 4; pr++) {
                uint32_t bd = bBase +
                    ((bRowBase + pr * 16) * 5 + kk * 2 + bChk) * 16;
                uint32_t r0, r1, r2, r3;
                ldsm4(r0, r1, r2, r3, bd);
                bf[2 * pr][0] = r0; bf[2 * pr][1] = r1;
                bf[2 * pr + 1][0] = r2; bf[2 * pr + 1][1] = r3;
            }
#pragma unroll
            for (int mt = 0; mt < 2; mt++)
#pragma unroll
                for (int nt = 0; nt < 8; nt++)
                    mma16816(acc[mt][nt], af[mt], bf[nt]);
        }

        if (s + 3 < NS) LOAD_SLAB((s + 3) & 3, (s + 3) * 32);
        CP_COMMIT();
    }

    const int g  = lane >> 2;
    const int t4 = lane & 3;
#pragma unroll
    for (int nt = 0; nt < 8; nt++) {
        const int col = n0 + wn * 64 + nt * 8 + 2 * t4;
        float2 bb = *(const float2*)(bias + col);
#pragma unroll
        for (int mt = 0; mt < 2; mt++) {
            size_t row0 = m0 + wm * 32 + mt * 16 + g;
            float v00 = acc[mt][nt][0] + bb.x, v01 = acc[mt][nt][1] + bb.y;
            float v10 = acc[mt][nt][2] + bb.x, v11 = acc[mt][nt][3] + bb.y;
            if constexpr (sizeof(OT) == 4) {
                *(float2*)((float*)C + row0 * N + col) = make_float2(v00, v01);
                *(float2*)((float*)C + (row0 + 8) * N + col) = make_float2(v10, v11);
            } else {
                *(__half2*)((__half*)C + row0 * N + col) =
                    __floats2half2_rn(v00, v01);
                *(__half2*)((__half*)C + (row0 + 8) * N + col) =
                    __floats2half2_rn(v10, v11);
            }
        }
    }
#undef LOAD_SLAB
}

// ======================= tensor-core attention ==============================
// Block = (window, head), 64 threads (2 warps). 49 tokens padded to 64.
__global__ void __launch_bounds__(64)
attn_mma(const __half* __restrict__ qkv, const float* __restrict__ table,
         __half* __restrict__ outp) {
    __shared__ __align__(16) __half Qs[64 * 40];
    __shared__ __align__(16) __half Ks[64 * 40];
    __shared__ __align__(16) __half Vs[64 * 40];
    __shared__ float Bs[169];
    __shared__ int   rowi[49];
    __shared__ int   cinfo[64];

    const int tid  = threadIdx.x;
    const int w    = tid >> 5;
    const int lane = tid & 31;
    const int head = blockIdx.x & 7;
    const int win  = blockIdx.x >> 3;
    const int b    = win >> 6;
    const int wr   = (win >> 3) & 7;
    const int wc   = win & 7;

    if (tid < 49) {
        int ih = tid / 7, iw = tid - ih * 7;
        int oh = wr * 7 + ih + 3; if (oh >= 56) oh -= 56;
        int ow = wc * 7 + iw + 3; if (ow >= 56) ow -= 56;
        rowi[tid] = (b * 56 + oh) * 56 + ow;
    }
    {
        int j = tid;
        int jh = j / 7, jw = j - jh * 7;
        int hj = wr * 7 + jh, wj = wc * 7 + jw;
        int rj = ((hj < 49) ? 0 : (hj < 53 ? 1 : 2)) * 3 +
                 ((wj < 49) ? 0 : (wj < 53 ? 1 : 2));
        cinfo[j] = (jh * 13 + jw) | (rj << 8) | ((j < 49 ? 0 : 1) << 15);
    }
    for (int t = tid; t < 169; t += 64) Bs[t] = table[t * 8 + head];
    for (int idx = tid; idx < 180; idx += 64) {
        int mat = idx / 60, rem = idx - mat * 60;
        int r = 49 + (rem >> 2), q = rem & 3;
        __half* base = (mat == 0) ? Qs : (mat == 1) ? Ks : Vs;
        *(uint4*)(base + r * 40 + q * 8) = make_uint4(0, 0, 0, 0);
    }
    __syncthreads();

    for (int idx = tid; idx < 196; idx += 64) {
        int p = idx >> 2, q = idx & 3;
        const __half* src = qkv + (size_t)rowi[p] * 768 + head * 32 + q * 8;
        *(uint4*)(Qs + p * 40 + q * 8) = *(const uint4*)(src);
        *(uint4*)(Ks + p * 40 + q * 8) = *(const uint4*)(src + 256);
        *(uint4*)(Vs + p * 40 + q * 8) = *(const uint4*)(src + 512);
    }
    __syncthreads();

    const uint32_t sQ = smem_u32(Qs), sK = smem_u32(Ks), sV = smem_u32(Vs);

    uint32_t aQ[2][2][4];
#pragma unroll
    for (int mt = 0; mt < 2; mt++)
#pragma unroll
        for (int kk = 0; kk < 2; kk++) {
            int row = w * 32 + mt * 16 + (lane & 15);
            uint32_t ad = sQ + row * 80 + (kk * 2 + (lane >> 4)) * 16;
            ldsm4(aQ[mt][kk][0], aQ[mt][kk][1], aQ[mt][kk][2], aQ[mt][kk][3], ad);
        }
    uint32_t bK[2][8][2];
#pragma unroll
    for (int kk = 0; kk < 2; kk++)
#pragma unroll
        for (int pr = 0; pr < 4; pr++) {
            int row = pr * 16 + (lane & 7) + ((lane >> 4) << 3);
            uint32_t ad = sK + row * 80 + (kk * 2 + ((lane >> 3) & 1)) * 16;
            uint32_t r0, r1, r2, r3;
            ldsm4(r0, r1, r2, r3, ad);
            bK[kk][2 * pr][0] = r0;     bK[kk][2 * pr][1] = r1;
            bK[kk][2 * pr + 1][0] = r2; bK[kk][2 * pr + 1][1] = r3;
        }
    float s[2][8][4];
#pragma unroll
    for (int mt = 0; mt < 2; mt++)
#pragma unroll
        for (int nt = 0; nt < 8; nt++) {
            s[mt][nt][0] = s[mt][nt][1] = s[mt][nt][2] = s[mt][nt][3] = 0.f;
            mma16816(s[mt][nt], aQ[mt][0], bK[0][nt]);
            mma16816(s[mt][nt], aQ[mt][1], bK[1][nt]);
        }

    const int g  = lane >> 2;
    const int t4 = lane & 3;
    const float scale = 0.17677669529663687f;

    int cp[16];
#pragma unroll
    for (int nt = 0; nt < 8; nt++) {
        cp[2 * nt]     = cinfo[nt * 8 + 2 * t4];
        cp[2 * nt + 1] = cinfo[nt * 8 + 2 * t4 + 1];
    }
    int   rb[2][2], ri[2][2];
    bool  rv[2][2];
#pragma unroll
    for (int mt = 0; mt < 2; mt++)
#pragma unroll
        for (int h = 0; h < 2; h++) {
            int i = w * 32 + mt * 16 + g + 8 * h;
            rv[mt][h] = (i < 49);
            int ih = i / 7, iw = i - ih * 7;
            if (!rv[mt][h]) { ih = 0; iw = 0; }
            rb[mt][h] = (ih + 6) * 13 + iw + 6;
            int hh = wr * 7 + ih, vv = wc * 7 + iw;
            ri[mt][h] = ((hh < 49) ? 0 : (hh < 53 ? 1 : 2)) * 3 +
                        ((vv < 49) ? 0 : (vv < 53 ? 1 : 2));
        }
#pragma unroll
    for (int mt = 0; mt < 2; mt++)
#pragma unroll
        for (int nt = 0; nt < 8; nt++)
#pragma unroll
            for (int e = 0; e < 4; e++) {
                int h = e >> 1, cs = e & 1;
                float v;
                if (!rv[mt][h]) v = 0.f;
                else {
                    int ci = cp[2 * nt + cs];
                    if (ci >> 15) v = -1e4f;
                    else {
                        v = s[mt][nt][e] * scale + Bs[rb[mt][h] - (ci & 0xFF)];
                        if (((ci >> 8) & 0xF) != ri[mt][h]) v -= 100.f;
                    }
                }
                s[mt][nt][e] = v;
            }

    float zinv[2][2];
#pragma unroll
    for (int mt = 0; mt < 2; mt++)
#pragma unroll
        for (int h = 0; h < 2; h++) {
            float m = -1e30f;
#pragma unroll
            for (int nt = 0; nt < 8; nt++) {
                m = fmaxf(m, s[mt][nt][2 * h]);
                m = fmaxf(m, s[mt][nt][2 * h + 1]);
            }
            m = fmaxf(m, __shfl_xor_sync(0xffffffffu, m, 1));
            m = fmaxf(m, __shfl_xor_sync(0xffffffffu, m, 2));
            float sum = 0.f;
#pragma unroll
            for (int nt = 0; nt < 8; nt++) {
                float e0 = __expf(s[mt][nt][2 * h] - m);
                float e1 = __expf(s[mt][nt][2 * h + 1] - m);
                s[mt][nt][2 * h] = e0;
                s[mt][nt][2 * h + 1] = e1;
                sum += e0 + e1;
            }
            sum += __shfl_xor_sync(0xffffffffu, sum, 1);
            sum += __shfl_xor_sync(0xffffffffu, sum, 2);
            zinv[mt][h] = 1.0f / sum;
        }

    uint32_t aP[2][4][4];
#pragma unroll
    for (int mt = 0; mt < 2; mt++)
#pragma unroll
        for (int kt = 0; kt < 4; kt++) {
            aP[mt][kt][0] = h2u(__floats2half2_rn(s[mt][2 * kt][0],
                                                  s[mt][2 * kt][1]));
            aP[mt][kt][1] = h2u(__floats2half2_rn(s[mt][2 * kt][2],
                                                  s[mt][2 * kt][3]));
            aP[mt][kt][2] = h2u(__floats2half2_rn(s[mt][2 * kt + 1][0],
                                                  s[mt][2 * kt + 1][1]));
            aP[mt][kt][3] = h2u(__floats2half2_rn(s[mt][2 * kt + 1][2],
                                                  s[mt][2 * kt + 1][3]));
        }

    uint32_t bV[4][4][2];
#pragma unroll
    for (int kt = 0; kt < 4; kt++)
#pragma unroll
        for (int nh = 0; nh < 2; nh++) {
            int row = kt * 16 + (lane & 7) + (((lane >> 3) & 1) << 3);
            uint32_t ad = sV + row * 80 + nh * 32 + ((lane >> 4) << 4);
            uint32_t r0, r1, r2, r3;
            ldsm4t(r0, r1, r2, r3, ad);
            bV[kt][2 * nh][0] = r0;     bV[kt][2 * nh][1] = r1;
            bV[kt][2 * nh + 1][0] = r2; bV[kt][2 * nh + 1][1] = r3;
        }

    float o[2][4][4];
#pragma unroll
    for (int mt = 0; mt < 2; mt++)
#pragma unroll
        for (int vn = 0; vn < 4; vn++) {
            o[mt][vn][0] = o[mt][vn][1] = o[mt][vn][2] = o[mt][vn][3] = 0.f;
#pragma unroll
            for (int kt = 0; kt < 4; kt++)
                mma16816(o[mt][vn], aP[mt][kt], bV[kt][vn]);
        }

#pragma unroll
    for (int mt = 0; mt < 2; mt++)
#pragma unroll
        for (int h = 0; h < 2; h++) {
            int i = w * 32 + mt * 16 + g + 8 * h;
            if (i >= 49) continue;
            float rz = zinv[mt][h];
            __half* dst = outp + (size_t)rowi[i] * KC + head * 32;
#pragma unroll
            for (int vn = 0; vn < 4; vn++) {
                int col = vn * 8 + 2 * t4;
                *(__half2*)(dst + col) =
                    __floats2half2_rn(o[mt][vn][2 * h] * rz,
                                      o[mt][vn][2 * h + 1] * rz);
            }
        }
}

// ---------------------------------------------------------------------------
extern "C" void kernel_launch(void* const* d_in, const int* in_sizes, int n_in,
                              void* d_out, int out_size) {
    const float* x      = (const float*)d_in[0];
    const float* qkv_w  = (const float*)d_in[1];
    const float* qkv_b  = (const float*)d_in[2];
    const float* proj_w = (const float*)d_in[3];
    const float* proj_b = (const float*)d_in[4];
    const float* table  = (const float*)d_in[5];
    float* out = (float*)d_out;

    void *qkv_p, *x16_p, *acat_p, *wq_p, *wp_p;
    cudaGetSymbolAddress(&qkv_p,  g_qkv);
    cudaGetSymbolAddress(&x16_p,  g_x16);
    cudaGetSymbolAddress(&acat_p, g_acat);
    cudaGetSymbolAddress(&wq_p,   g_wq);
    cudaGetSymbolAddress(&wp_p,   g_wp);
    __half* qkv  = (__half*)qkv_p;
    __half* x16  = (__half*)x16_p;
    __half* acat = (__half*)acat_p;
    __half* wq   = (__half*)wq_p;
    __half* wp   = (__half*)wp_p;

    static bool attr_done = false;
    if (!attr_done) {
        cudaFuncSetAttribute(gemm_mma<__half>,
                             cudaFuncAttributeMaxDynamicSharedMemorySize,
                             GEMM_SMEM);
        cudaFuncSetAttribute(gemm_mma<float>,
                             cudaFuncAttributeMaxDynamicSharedMemorySize,
                             GEMM_SMEM);
        attr_done = true;
    }

    convert_h<<<(M_ROWS * 64 + 255) / 256, 256>>>(x, x16, M_ROWS * 64);
    convert_h<<<(768 * 64 + 255) / 256, 256>>>(qkv_w, wq, 768 * 64);
    convert_h<<<(256 * 64 + 255) / 256, 256>>>(proj_w, wp, 256 * 64);

    dim3 gq(768 / 128, M_ROWS / 128);
    gemm_mma<__half><<<gq, 256, GEMM_SMEM>>>(x16, wq, qkv_b, qkv, 768);

    attn_mma<<<2048 * 8, 64>>>(qkv, table, acat);

    dim3 gp(256 / 128, M_ROWS / 128);
    gemm_mma<float><<<gp, 256, GEMM_SMEM>>>(acat, wp, proj_b, out, 256);
}